// round 14
// baseline (speedup 1.0000x reference)
#include <cuda_runtime.h>
#include <cuda_bf16.h>
#include <cuda_fp16.h>

#define NN    100000
#define NE    1600000
#define NG    64
#define FIN   128
#define HH    64
#define H2    128
#define IMGF  50176
#define MLP0  1024
#define NC    38

typedef unsigned long long u64;
typedef unsigned int u32;
typedef unsigned short u16;

// ---------------- scratch (device globals; no allocation allowed) ----------------
__device__ __align__(16) __half g_hp1h[(size_t)NN * H2];   // transform1 out (fp16)
__device__ __align__(16) __half g_a1h [(size_t)NN * H2];   // conv1 out (fp16)
__device__ __align__(16) __half g_hp2h[(size_t)NN * HH];   // transform2 out (fp16)
__device__ __align__(16) float  g_a2 [(size_t)NN * HH];    // conv2 out (fp32)
__device__ int   g_cnt[NN];
__device__ int   g_fill[NN];
__device__ int   g_rowstart[NN + 1];
__device__ int   g_srclist[NE];
__device__ float g_dinv[NN];
__device__ int   g_bsum[128];
__device__ int   g_gstart[NG + 1];
__device__ float g_x0a[NG * MLP0];
__device__ float g_x0 [NG * HH];
__device__ float g_pool[NG * HH];

// ---------------- packed f32x2 helpers ----------------
__device__ __forceinline__ u64 pack_dup(float a) {
    u64 r; asm("mov.b64 %0, {%1, %1};" : "=l"(r) : "f"(a)); return r;
}
__device__ __forceinline__ u64 pack2(float lo, float hi) {
    u64 r; asm("mov.b64 %0, {%1, %2};" : "=l"(r) : "f"(lo), "f"(hi)); return r;
}
__device__ __forceinline__ u64 ffma2(u64 a, u64 b, u64 c) {
    u64 d; asm("fma.rn.f32x2 %0, %1, %2, %3;" : "=l"(d) : "l"(a), "l"(b), "l"(c)); return d;
}
__device__ __forceinline__ void unpack2(u64 v, float& lo, float& hi) {
    asm("mov.b64 {%0, %1}, %2;" : "=f"(lo), "=f"(hi) : "l"(v));
}

// ---------------- mma / ldmatrix helpers (fp16 path) ----------------
__device__ __forceinline__ u32 smem_u32(const void* p) {
    u32 a;
    asm("{ .reg .u64 t; cvta.to.shared.u64 t, %1; cvt.u32.u64 %0, t; }" : "=r"(a) : "l"(p));
    return a;
}
__device__ __forceinline__ void ldsm_x4(u32& r0, u32& r1, u32& r2, u32& r3, u32 addr) {
    asm volatile("ldmatrix.sync.aligned.m8n8.x4.shared.b16 {%0,%1,%2,%3}, [%4];"
                 : "=r"(r0), "=r"(r1), "=r"(r2), "=r"(r3) : "r"(addr));
}
__device__ __forceinline__ void ldsm_x4t(u32& r0, u32& r1, u32& r2, u32& r3, u32 addr) {
    asm volatile("ldmatrix.sync.aligned.m8n8.x4.trans.shared.b16 {%0,%1,%2,%3}, [%4];"
                 : "=r"(r0), "=r"(r1), "=r"(r2), "=r"(r3) : "r"(addr));
}
__device__ __forceinline__ void mma_f16(float c[4], const u32 a[4], u32 b0, u32 b1) {
    asm volatile(
        "mma.sync.aligned.m16n8k16.row.col.f32.f16.f16.f32 "
        "{%0,%1,%2,%3}, {%4,%5,%6,%7}, {%8,%9}, {%0,%1,%2,%3};"
        : "+f"(c[0]), "+f"(c[1]), "+f"(c[2]), "+f"(c[3])
        : "r"(a[0]), "r"(a[1]), "r"(a[2]), "r"(a[3]), "r"(b0), "r"(b1));
}
__device__ __forceinline__ u32 cvt2h(float x, float y) {
    __half2 h = __floats2half2_rn(x, y);
    return *(u32*)&h;
}
__device__ __forceinline__ void split2h(float x, float y, u32& h, u32& l) {
    __half2 hh = __floats2half2_rn(x, y);
    float bx = __low2float(hh), by = __high2float(hh);
    __half2 ll = __floats2half2_rn(x - bx, y - by);
    h = *(u32*)&hh; l = *(u32*)&ll;
}
__device__ __forceinline__ void cvt8f(uint4 v, float f[8]) {
    float2 a0 = __half22float2(*(__half2*)&v.x);
    float2 a1 = __half22float2(*(__half2*)&v.y);
    float2 a2 = __half22float2(*(__half2*)&v.z);
    float2 a3 = __half22float2(*(__half2*)&v.w);
    f[0] = a0.x; f[1] = a0.y; f[2] = a1.x; f[3] = a1.y;
    f[4] = a2.x; f[5] = a2.y; f[6] = a3.x; f[7] = a3.y;
}

// ---------------- init ----------------
__global__ void init_kernel(const float* __restrict__ bm0, const float* __restrict__ bm1) {
    int i = blockIdx.x * blockDim.x + threadIdx.x;
    if (i < NN) { g_cnt[i] = 0; g_fill[i] = 0; }
    if (i < NG * MLP0) g_x0a[i] = bm0[i & (MLP0 - 1)];
    if (i < NG * HH)   g_x0[i] = bm1[i & (HH - 1)];
}

// ---------------- degree histogram ----------------
__global__ void deg_kernel(const int* __restrict__ dst) {
    int e = blockIdx.x * blockDim.x + threadIdx.x;
    if (e < NE) atomicAdd(&g_cnt[dst[e]], 1);
}

// ---------------- exclusive scan (3-phase) ----------------
__global__ void scan1_kernel() {
    __shared__ int sd[1024];
    int t = threadIdx.x;
    int idx = blockIdx.x * 1024 + t;
    int v = (idx < NN) ? g_cnt[idx] : 0;
    sd[t] = v;
    __syncthreads();
    for (int off = 1; off < 1024; off <<= 1) {
        int add = (t >= off) ? sd[t - off] : 0;
        __syncthreads();
        sd[t] += add;
        __syncthreads();
    }
    if (idx < NN) g_rowstart[idx] = sd[t] - v;
    if (t == 1023) g_bsum[blockIdx.x] = sd[t];
}
__global__ void scan2_kernel() {
    __shared__ int sd[128];
    int t = threadIdx.x;
    int v = (t < 98) ? g_bsum[t] : 0;
    sd[t] = v;
    __syncthreads();
    for (int off = 1; off < 128; off <<= 1) {
        int add = (t >= off) ? sd[t - off] : 0;
        __syncthreads();
        sd[t] += add;
        __syncthreads();
    }
    if (t < 98) g_bsum[t] = sd[t] - v;
}
__global__ void scan3_kernel() {
    int idx = blockIdx.x * 1024 + threadIdx.x;
    if (idx < NN) {
        g_rowstart[idx] += g_bsum[blockIdx.x];
        g_dinv[idx] = rsqrtf((float)(g_cnt[idx] + 1));
    }
    if (idx == 0) g_rowstart[NN] = NE;
}

// ---------------- CSR fill ----------------
__global__ void fill_kernel(const int* __restrict__ src, const int* __restrict__ dst) {
    int e = blockIdx.x * blockDim.x + threadIdx.x;
    if (e < NE) {
        int d = dst[e];
        int p = g_rowstart[d] + atomicAdd(&g_fill[d], 1);
        g_srclist[p] = src[e];
    }
}

// ---------------- fp16 MMA GEMM --------------------------------------------------
// C[M,N] (+)= A[M,K] @ B[K,N]. B single fp16.
// AHALF=0: A fp32, split hi+lo fp16 (2-term). AHALF=1: A already fp16 (1-term).
// BM=64, BK=32, double-buffered smem, single-deep reg prefetch.
// 8 warps as 4(wm) x 2(wn); warp tile m16 x (BN/2). MINB: min blocks/SM (reg cap).
#define APAD 40
template<int BN, bool ATOMIC, bool HALF_OUT, bool AHALF, int MINB>
__global__ void __launch_bounds__(256, MINB)
mma_gemm_kernel(const void* __restrict__ Av, int lda,
                const float* __restrict__ B, int ldb,
                float* __restrict__ C, int ldc,
                int M, int K, int kPerSplit)
{
    constexpr int BK    = 32;
    constexpr int WNT   = BN / 2;
    constexpr int NB    = WNT / 16;
    constexpr int BPADT = BN + 8;
    constexpr int BREG  = BN / 32;

    __shared__ __align__(16) u16 sAh[2][64][APAD];
    __shared__ __align__(16) u16 sAl[AHALF ? 1 : 2][AHALF ? 1 : 64][AHALF ? 1 : APAD];
    __shared__ __align__(16) u16 sB [2][32][BPADT];

    const int tid  = threadIdx.x;
    const int lane = tid & 31, wid = tid >> 5;
    const int wm = wid & 3, wn = wid >> 2;
    const int m0 = blockIdx.y * 64;
    const int n0 = blockIdx.x * BN;
    const int k0 = blockIdx.z * kPerSplit;
    const int kend = k0 + kPerSplit;     // exact splits

    const float* Af = (const float*)Av;
    const __half* Ah = (const __half*)Av;
    const int ar0 = tid >> 3, ac = (tid & 7) * 4;
    const int arh = tid >> 2, ach = (tid & 3) * 8;

    float4 aR[2]; uint4 aRh; float4 bR[BREG];
    auto ldg_tile = [&](int kb) {
        if (AHALF) {
            int m = m0 + arh;
            if (m < M) aRh = *(const uint4*)&Ah[(size_t)m * lda + kb + ach];
            else       aRh = make_uint4(0, 0, 0, 0);
        } else {
#pragma unroll
            for (int t = 0; t < 2; t++) {
                int m = m0 + ar0 + 32 * t;
                if (m < M) aR[t] = *(const float4*)&Af[(size_t)m * lda + kb + ac];
                else       aR[t] = make_float4(0.f, 0.f, 0.f, 0.f);
            }
        }
#pragma unroll
        for (int t = 0; t < BREG; t++) {
            int i4 = tid + t * 256;
            int r = i4 / (BN / 4), c4 = i4 % (BN / 4);
            bR[t] = *(const float4*)&B[(size_t)(kb + r) * ldb + n0 + c4 * 4];
        }
    };
    auto sts_tile = [&](int buf) {
        if (AHALF) {
            *(uint4*)&sAh[buf][arh][ach] = aRh;
        } else {
#pragma unroll
            for (int t = 0; t < 2; t++) {
                int r = ar0 + 32 * t;
                u32 h0, h1, l0, l1;
                split2h(aR[t].x, aR[t].y, h0, l0);
                split2h(aR[t].z, aR[t].w, h1, l1);
                *(u64*)&sAh[buf][r][ac] = (u64)h0 | ((u64)h1 << 32);
                *(u64*)&sAl[buf][r][ac] = (u64)l0 | ((u64)l1 << 32);
            }
        }
#pragma unroll
        for (int t = 0; t < BREG; t++) {
            int i4 = tid + t * 256;
            int r = i4 / (BN / 4), c4 = i4 % (BN / 4);
            u32 h0 = cvt2h(bR[t].x, bR[t].y);
            u32 h1 = cvt2h(bR[t].z, bR[t].w);
            *(u64*)&sB[buf][r][c4 * 4] = (u64)h0 | ((u64)h1 << 32);
        }
    };

    const int g = lane >> 3, lr = lane & 7;
    const u32 baseAh = smem_u32(sAh), baseAl = smem_u32(sAl), baseB = smem_u32(sB);
    const u32 offA = (u32)(((16 * wm + lr + 8 * (g & 1)) * APAD + 8 * (g >> 1)) * 2);
    const u32 offB = (u32)(((lr + 8 * (g & 1)) * BPADT + WNT * wn + 8 * (g >> 1)) * 2);
    constexpr u32 ABUF = sizeof(u16) * 64 * APAD;
    constexpr u32 BBUF = sizeof(u16) * 32 * BPADT;

    float c[2 * NB][4];
#pragma unroll
    for (int s = 0; s < 2 * NB; s++)
#pragma unroll
        for (int i = 0; i < 4; i++) c[s][i] = 0.0f;

    ldg_tile(k0);
    sts_tile(0);
    __syncthreads();

    int buf = 0;
    for (int kb = k0; kb < kend; kb += BK) {
        bool has_next = (kb + BK) < kend;
        if (has_next) ldg_tile(kb + BK);

#pragma unroll
        for (int ks = 0; ks < 2; ks++) {
            u32 ah[4], al[4];
            u32 adA = offA + buf * ABUF + ks * 32;
            ldsm_x4(ah[0], ah[1], ah[2], ah[3], baseAh + adA);
            if (!AHALF) ldsm_x4(al[0], al[1], al[2], al[3], baseAl + adA);
#pragma unroll
            for (int nb = 0; nb < NB; nb++) {
                u32 bh[4];
                u32 adB = offB + buf * BBUF + ks * (16 * BPADT * 2) + nb * 32;
                ldsm_x4t(bh[0], bh[1], bh[2], bh[3], baseB + adB);
                mma_f16(c[2 * nb],     ah, bh[0], bh[1]);
                mma_f16(c[2 * nb + 1], ah, bh[2], bh[3]);
                if (!AHALF) {
                    mma_f16(c[2 * nb],     al, bh[0], bh[1]);
                    mma_f16(c[2 * nb + 1], al, bh[2], bh[3]);
                }
            }
        }
        if (has_next) sts_tile(buf ^ 1);
        __syncthreads();
        buf ^= 1;
    }

    // ---- epilogue ----
    const int row = m0 + 16 * wm + (lane >> 2);
    const int colb = n0 + WNT * wn + 2 * (lane & 3);
    __half* Ch = (__half*)C;
#pragma unroll
    for (int rr = 0; rr < 2; rr++) {
        int r = row + 8 * rr;
        if (r >= M) continue;
#pragma unroll
        for (int s = 0; s < 2 * NB; s++) {
            int col = colb + 8 * s;
            if (ATOMIC) {
                atomicAdd(&C[(size_t)r * ldc + col],     c[s][2 * rr]);
                atomicAdd(&C[(size_t)r * ldc + col + 1], c[s][2 * rr + 1]);
            } else if (HALF_OUT) {
                __half2 hv = __floats2half2_rn(c[s][2 * rr], c[s][2 * rr + 1]);
                *(__half2*)&Ch[(size_t)r * ldc + col] = hv;
            } else {
                *(float2*)&C[(size_t)r * ldc + col] =
                    make_float2(c[s][2 * rr], c[s][2 * rr + 1]);
            }
        }
    }
}

// ---------------- gemm3: f32x2 tiles (MLP2 only) ----------------------------------
template<int BM, int BN, int TM, int TN, bool ATOMIC>
__global__ void __launch_bounds__(256)
gemm3_kernel(const float* __restrict__ A, int lda,
             const float* __restrict__ B, int ldb,
             float* __restrict__ C, int ldc,
             int M, int N, int K, int kPerSplit)
{
    constexpr int BK = 16;
    constexpr int AREG = BM * BK / (256 * 4);
    constexpr int BREG = BK * BN / (256 * 4);
    __shared__ float  As[BK][BM + 4];
    __shared__ float4 Bs4[BK][BN / 4];

    const int tid = threadIdx.x;
    const int tx = tid & 15, ty = tid >> 4;
    const int m0 = blockIdx.y * BM;
    const int n0 = blockIdx.x * BN;
    const int k0 = blockIdx.z * kPerSplit;
    int kend = k0 + kPerSplit; if (kend > K) kend = K;

    float4 aR[AREG], bR[BREG];

    auto ldg_tile = [&](int kb) {
#pragma unroll
        for (int t = 0; t < AREG; t++) {
            int i4 = tid + t * 256;
            int r = i4 >> 2, c = (i4 & 3) * 4;
            int m = m0 + r;
            if (m < M) aR[t] = *(const float4*)&A[(size_t)m * lda + kb + c];
            else       aR[t] = make_float4(0.f, 0.f, 0.f, 0.f);
        }
#pragma unroll
        for (int t = 0; t < BREG; t++) {
            int i4 = tid + t * 256;
            int r = i4 / (BN / 4), c4 = i4 % (BN / 4);
            bR[t] = *(const float4*)&B[(size_t)(kb + r) * ldb + n0 + c4 * 4];
        }
    };
    auto sts_tile = [&]() {
#pragma unroll
        for (int t = 0; t < AREG; t++) {
            int i4 = tid + t * 256;
            int r = i4 >> 2, c = (i4 & 3) * 4;
            As[c + 0][r] = aR[t].x; As[c + 1][r] = aR[t].y;
            As[c + 2][r] = aR[t].z; As[c + 3][r] = aR[t].w;
        }
#pragma unroll
        for (int t = 0; t < BREG; t++) {
            int i4 = tid + t * 256;
            Bs4[i4 / (BN / 4)][i4 % (BN / 4)] = bR[t];
        }
    };

    u64 acc[TM][TN / 2];
#pragma unroll
    for (int i = 0; i < TM; i++)
#pragma unroll
        for (int j = 0; j < TN / 2; j++) acc[i][j] = 0ull;

    ldg_tile(k0);
    sts_tile();
    __syncthreads();

    for (int kb = k0; kb < kend; kb += BK) {
        bool has_next = (kb + BK) < kend;
        if (has_next) ldg_tile(kb + BK);

#pragma unroll
        for (int k = 0; k < BK; k++) {
            u64 bp[TN / 2];
#pragma unroll
            for (int j = 0; j < TN / 4; j++) {
                float4 bv = Bs4[k][tx + 16 * j];
                bp[2 * j]     = pack2(bv.x, bv.y);
                bp[2 * j + 1] = pack2(bv.z, bv.w);
            }
            float av[TM];
#pragma unroll
            for (int q = 0; q < TM / 4; q++) {
                float4 a4 = *(const float4*)&As[k][ty * TM + 4 * q];
                av[4 * q + 0] = a4.x; av[4 * q + 1] = a4.y;
                av[4 * q + 2] = a4.z; av[4 * q + 3] = a4.w;
            }
#pragma unroll
            for (int i = 0; i < TM; i++) {
                u64 ap = pack_dup(av[i]);
#pragma unroll
                for (int j = 0; j < TN / 2; j++)
                    acc[i][j] = ffma2(ap, bp[j], acc[i][j]);
            }
        }
        __syncthreads();
        if (has_next) {
            sts_tile();
            __syncthreads();
        }
    }

#pragma unroll
    for (int i = 0; i < TM; i++) {
        int m = m0 + ty * TM + i;
        if (m >= M) continue;
#pragma unroll
        for (int j = 0; j < TN / 4; j++) {
            int col = n0 + tx * 4 + 64 * j;
            float x0, x1, x2, x3;
            unpack2(acc[i][2 * j],     x0, x1);
            unpack2(acc[i][2 * j + 1], x2, x3);
            if (ATOMIC) {
                float* crow = C + (size_t)m * ldc + col;
                atomicAdd(crow + 0, x0);
                atomicAdd(crow + 1, x1);
                atomicAdd(crow + 2, x2);
                atomicAdd(crow + 3, x3);
            } else {
                *(float4*)&C[(size_t)m * ldc + col] = make_float4(x0, x1, x2, x3);
            }
        }
    }
}

// ---- agg1 v2 (fp16 in/out, LDG.128 gather): half-warp per edge row --------------
// warp per node; lanes split 16/16 over 2 edges per step; lane covers 8 columns.
__global__ void agg128_kernel(const __half* __restrict__ hp, const float* __restrict__ bias,
                              __half* __restrict__ out) {
    int gw   = (blockIdx.x * blockDim.x + threadIdx.x) >> 5;
    int lane = threadIdx.x & 31;
    if (gw >= NN) return;
    int r0 = g_rowstart[gw], r1 = g_rowstart[gw + 1];
    float dn = g_dinv[gw];
    const int half = lane >> 4, sl = lane & 15;
    const uint4* h16 = (const uint4*)hp;          // 16 uint4 per 128-col row

    float acc[8];
    if (half == 0) {
        float f[8]; cvt8f(h16[(size_t)gw * 16 + sl], f);
#pragma unroll
        for (int i = 0; i < 8; i++) acc[i] = f[i] * dn;
    } else {
#pragma unroll
        for (int i = 0; i < 8; i++) acc[i] = 0.0f;
    }

    for (int e = r0; e < r1; e += 2) {
        int e0 = e + half;
        if (e0 < r1) {
            int s = g_srclist[e0];
            float d = g_dinv[s];
            float f[8]; cvt8f(h16[(size_t)s * 16 + sl], f);
#pragma unroll
            for (int i = 0; i < 8; i++) acc[i] = fmaf(f[i], d, acc[i]);
        }
    }
#pragma unroll
    for (int i = 0; i < 8; i++)
        acc[i] += __shfl_down_sync(0xFFFFFFFFu, acc[i], 16);

    if (half == 0) {
        float4 b0 = ((const float4*)bias)[2 * sl];
        float4 b1 = ((const float4*)bias)[2 * sl + 1];
        float o[8];
        o[0] = fmaxf(fmaf(acc[0], dn, b0.x), 0.0f);
        o[1] = fmaxf(fmaf(acc[1], dn, b0.y), 0.0f);
        o[2] = fmaxf(fmaf(acc[2], dn, b0.z), 0.0f);
        o[3] = fmaxf(fmaf(acc[3], dn, b0.w), 0.0f);
        o[4] = fmaxf(fmaf(acc[4], dn, b1.x), 0.0f);
        o[5] = fmaxf(fmaf(acc[5], dn, b1.y), 0.0f);
        o[6] = fmaxf(fmaf(acc[6], dn, b1.z), 0.0f);
        o[7] = fmaxf(fmaf(acc[7], dn, b1.w), 0.0f);
        uint4 pv;
        pv.x = cvt2h(o[0], o[1]); pv.y = cvt2h(o[2], o[3]);
        pv.z = cvt2h(o[4], o[5]); pv.w = cvt2h(o[6], o[7]);
        ((uint4*)out)[(size_t)gw * 16 + sl] = pv;
    }
}

// ---- agg2 v2 (fp16 in, fp32 out): quarter-warp per edge row ----------------------
__global__ void agg64_kernel(const __half* __restrict__ hp, const float* __restrict__ bias,
                             float* __restrict__ out) {
    int gw   = (blockIdx.x * blockDim.x + threadIdx.x) >> 5;
    int lane = threadIdx.x & 31;
    if (gw >= NN) return;
    int r0 = g_rowstart[gw], r1 = g_rowstart[gw + 1];
    float dn = g_dinv[gw];
    const int q = lane >> 3, sl = lane & 7;
    const uint4* h8 = (const uint4*)hp;           // 8 uint4 per 64-col row

    float acc[8];
    if (q == 0) {
        float f[8]; cvt8f(h8[(size_t)gw * 8 + sl], f);
#pragma unroll
        for (int i = 0; i < 8; i++) acc[i] = f[i] * dn;
    } else {
#pragma unroll
        for (int i = 0; i < 8; i++) acc[i] = 0.0f;
    }

    for (int e = r0; e < r1; e += 4) {
        int e0 = e + q;
        if (e0 < r1) {
            int s = g_srclist[e0];
            float d = g_dinv[s];
            float f[8]; cvt8f(h8[(size_t)s * 8 + sl], f);
#pragma unroll
            for (int i = 0; i < 8; i++) acc[i] = fmaf(f[i], d, acc[i]);
        }
    }
#pragma unroll
    for (int i = 0; i < 8; i++) {
        acc[i] += __shfl_down_sync(0xFFFFFFFFu, acc[i], 16);
        acc[i] += __shfl_down_sync(0xFFFFFFFFu, acc[i], 8);
    }

    if (q == 0) {
        float4 b0 = ((const float4*)bias)[2 * sl];
        float4 b1 = ((const float4*)bias)[2 * sl + 1];
        float4 o0, o1;
        o0.x = fmaxf(fmaf(acc[0], dn, b0.x), 0.0f);
        o0.y = fmaxf(fmaf(acc[1], dn, b0.y), 0.0f);
        o0.z = fmaxf(fmaf(acc[2], dn, b0.z), 0.0f);
        o0.w = fmaxf(fmaf(acc[3], dn, b0.w), 0.0f);
        o1.x = fmaxf(fmaf(acc[4], dn, b1.x), 0.0f);
        o1.y = fmaxf(fmaf(acc[5], dn, b1.y), 0.0f);
        o1.z = fmaxf(fmaf(acc[6], dn, b1.z), 0.0f);
        o1.w = fmaxf(fmaf(acc[7], dn, b1.w), 0.0f);
        ((float4*)out)[(size_t)gw * 16 + 2 * sl]     = o0;
        ((float4*)out)[(size_t)gw * 16 + 2 * sl + 1] = o1;
    }
}

// ---------------- per-graph node ranges (batch is sorted) ----------------
__global__ void gstart_kernel(const int* __restrict__ batch) {
    int g = threadIdx.x;
    if (g > NG) return;
    int lo = 0, hi = NN;
    while (lo < hi) { int mid = (lo + hi) >> 1; if (batch[mid] < g) lo = mid + 1; else hi = mid; }
    g_gstart[g] = lo;
}

// ---------------- global_add_pool (atomic-free, block per graph) ----------------
__global__ void pool_kernel() {
    __shared__ float sm[4][HH];
    int b   = blockIdx.x;
    int f   = threadIdx.x & 63;
    int sub = threadIdx.x >> 6;
    int n0  = g_gstart[b], n1 = g_gstart[b + 1];
    float acc = 0.0f;
    for (int node = n0 + sub; node < n1; node += 4)
        acc += g_a2[(size_t)node * HH + f];
    sm[sub][f] = acc;
    __syncthreads();
    if (sub == 0)
        g_pool[b * HH + f] = sm[0][f] + sm[1][f] + sm[2][f] + sm[3][f];
}

// ---------------- head: Wmx + concat + Wfc + log_softmax ----------------
__global__ void final_kernel(const float* __restrict__ Wmx, const float* __restrict__ bmx,
                             const float* __restrict__ Wfc, const float* __restrict__ bfc,
                             float* __restrict__ out) {
    int b = blockIdx.x;
    int t = threadIdx.x;
    __shared__ float xt[2 * HH];
    __shared__ float pr[HH];
    __shared__ float lg[NC];
    __shared__ float s_lse;
    pr[t] = g_pool[b * HH + t];
    xt[t] = g_x0[b * HH + t];
    __syncthreads();
    float acc = bmx[t];
    for (int k = 0; k < HH; k++) acc = fmaf(pr[k], Wmx[k * HH + t], acc);
    xt[HH + t] = acc;
    __syncthreads();
    if (t < NC) {
        float l = bfc[t];
        for (int k = 0; k < 2 * HH; k++) l = fmaf(xt[k], Wfc[k * NC + t], l);
        lg[t] = l;
    }
    __syncthreads();
    if (t == 0) {
        float m = -1e30f;
        for (int j = 0; j < NC; j++) m = fmaxf(m, lg[j]);
        float s = 0.0f;
        for (int j = 0; j < NC; j++) s += expf(lg[j] - m);
        s_lse = m + logf(s);
    }
    __syncthreads();
    if (t < NC) out[b * NC + t] = lg[t] - s_lse;
}

// ---------------- launch (multi-stream fork/join inside graph capture) ----------------
extern "C" void kernel_launch(void* const* d_in, const int* in_sizes, int n_in,
                              void* d_out, int out_size) {
    const float* x    = (const float*)d_in[0];
    const int*   ei   = (const int*)  d_in[1];
    const float* img  = (const float*)d_in[2];
    const int*   batch= (const int*)  d_in[3];
    const float* W1   = (const float*)d_in[4];
    const float* b1   = (const float*)d_in[5];
    const float* W2   = (const float*)d_in[6];
    const float* b2   = (const float*)d_in[7];
    const float* Wm0  = (const float*)d_in[8];
    const float* bm0  = (const float*)d_in[9];
    const float* Wm1  = (const float*)d_in[10];
    const float* bm1  = (const float*)d_in[11];
    const float* Wmx  = (const float*)d_in[12];
    const float* bmx  = (const float*)d_in[13];
    const float* Wfc  = (const float*)d_in[14];
    const float* bfc  = (const float*)d_in[15];
    float* out = (float*)d_out;
    const int* src = ei;
    const int* dst = ei + NE;

    __half *p_hp1h, *p_hp2h, *p_a1h;
    float *p_a2, *p_x0a, *p_x0;
    cudaGetSymbolAddress((void**)&p_hp1h, g_hp1h);
    cudaGetSymbolAddress((void**)&p_a1h,  g_a1h);
    cudaGetSymbolAddress((void**)&p_hp2h, g_hp2h);
    cudaGetSymbolAddress((void**)&p_a2,   g_a2);
    cudaGetSymbolAddress((void**)&p_x0a,  g_x0a);
    cudaGetSymbolAddress((void**)&p_x0,   g_x0);

    static cudaStream_t s1 = nullptr, s2 = nullptr;
    static cudaEvent_t evF = nullptr, ev1 = nullptr, ev2 = nullptr;
    if (!s1) {
        cudaStreamCreateWithFlags(&s1, cudaStreamNonBlocking);
        cudaStreamCreateWithFlags(&s2, cudaStreamNonBlocking);
        cudaEventCreateWithFlags(&evF, cudaEventDisableTiming);
        cudaEventCreateWithFlags(&ev1, cudaEventDisableTiming);
        cudaEventCreateWithFlags(&ev2, cudaEventDisableTiming);
    }

    // --- main stream: init, then fork ---
    init_kernel<<<(NN + 255) / 256, 256>>>(bm0, bm1);            // 1
    cudaEventRecord(evF, 0);
    cudaStreamWaitEvent(s1, evF, 0);
    cudaStreamWaitEvent(s2, evF, 0);

    deg_kernel <<<(NE + 255) / 256, 256>>>(dst);                 // 2 (main)
    scan1_kernel<<<98, 1024>>>();                                // 3 (main)

    // 4th submission = fp16 tensor-core image GEMM
    // x0a(=bm0) += img @ Wm0   [64,50176]@[50176,1024], split-K 56x896, 3 CTA/SM
    {
        dim3 grid(MLP0 / 128, 1, 56);
        mma_gemm_kernel<128, true, false, false, 3><<<grid, 256, 0, s2>>>(
            img, IMGF, Wm0, MLP0, p_x0a, MLP0, NG, IMGF, 896);
    }

    // stream s1: transform1 via fp16 MMA, fp16 out: hp1 = x @ W1
    {
        dim3 grid(1, (NN + 63) / 64, 1);
        mma_gemm_kernel<128, false, true, false, 1><<<grid, 256, 0, s1>>>(
            x, FIN, W1, H2, (float*)p_hp1h, H2, NN, FIN, FIN);
    }
    gstart_kernel<<<1, NG + 1, 0, s1>>>(batch);
    cudaEventRecord(ev1, s1);

    // main: finish CSR
    scan2_kernel<<<1, 128>>>();
    scan3_kernel<<<98, 1024>>>();
    fill_kernel<<<(NE + 255) / 256, 256>>>(src, dst);

    // s2: x0(=bm1) += x0a @ Wm1   [64,1024]@[1024,64], split-K 16
    {
        dim3 grid(1, 1, 16);
        gemm3_kernel<64, 64, 4, 4, true><<<grid, 256, 0, s2>>>(
            p_x0a, MLP0, Wm1, HH, p_x0, HH, NG, HH, MLP0, MLP0 / 16);
    }
    cudaEventRecord(ev2, s2);

    // join s1 into main, then conv chain
    cudaStreamWaitEvent(0, ev1, 0);
    agg128_kernel<<<(NN * 32 + 255) / 256, 256>>>(p_hp1h, b1, p_a1h);

    // transform2 via fp16 MMA (BN=64, fp16 A, fp16 out): hp2 = a1 @ W2
    {
        dim3 grid(1, (NN + 63) / 64, 1);
        mma_gemm_kernel<64, false, true, true, 1><<<grid, 256>>>(
            p_a1h, H2, W2, HH, (float*)p_hp2h, HH, NN, H2, H2);
    }
    agg64_kernel<<<(NN * 32 + 255) / 256, 256>>>(p_hp2h, b2, p_a2);
    pool_kernel<<<NG, 256>>>();

    // join s2 into main, then head
    cudaStreamWaitEvent(0, ev2, 0);
    final_kernel<<<NG, HH>>>(Wmx, bmx, Wfc, bfc, out);
}

// round 15
// speedup vs baseline: 1.0011x; 1.0011x over previous
#include <cuda_runtime.h>
#include <cuda_bf16.h>
#include <cuda_fp16.h>

#define NN    100000
#define NE    1600000
#define NG    64
#define FIN   128
#define HH    64
#define H2    128
#define IMGF  50176
#define MLP0  1024
#define NC    38

typedef unsigned long long u64;
typedef unsigned int u32;
typedef unsigned short u16;

// ---------------- scratch (device globals; no allocation allowed) ----------------
__device__ __align__(16) __half g_hp1h[(size_t)NN * H2];   // transform1 out (fp16)
__device__ __align__(16) __half g_a1h [(size_t)NN * H2];   // conv1 out (fp16)
__device__ __align__(16) __half g_hp2h[(size_t)NN * HH];   // transform2 out (fp16)
__device__ __align__(16) float  g_a2 [(size_t)NN * HH];    // conv2 out (fp32)
__device__ int   g_cnt[NN];
__device__ int   g_fill[NN];
__device__ int   g_rowstart[NN + 1];
__device__ int   g_srclist[NE];
__device__ float g_dinv[NN];
__device__ int   g_bsum[128];
__device__ int   g_gstart[NG + 1];
__device__ float g_x0a[NG * MLP0];
__device__ float g_x0 [NG * HH];
__device__ float g_pool[NG * HH];

// ---------------- packed f32x2 helpers ----------------
__device__ __forceinline__ u64 pack_dup(float a) {
    u64 r; asm("mov.b64 %0, {%1, %1};" : "=l"(r) : "f"(a)); return r;
}
__device__ __forceinline__ u64 pack2(float lo, float hi) {
    u64 r; asm("mov.b64 %0, {%1, %2};" : "=l"(r) : "f"(lo), "f"(hi)); return r;
}
__device__ __forceinline__ u64 ffma2(u64 a, u64 b, u64 c) {
    u64 d; asm("fma.rn.f32x2 %0, %1, %2, %3;" : "=l"(d) : "l"(a), "l"(b), "l"(c)); return d;
}
__device__ __forceinline__ void unpack2(u64 v, float& lo, float& hi) {
    asm("mov.b64 {%0, %1}, %2;" : "=f"(lo), "=f"(hi) : "l"(v));
}

// ---------------- mma / ldmatrix helpers (fp16 path) ----------------
__device__ __forceinline__ u32 smem_u32(const void* p) {
    u32 a;
    asm("{ .reg .u64 t; cvta.to.shared.u64 t, %1; cvt.u32.u64 %0, t; }" : "=r"(a) : "l"(p));
    return a;
}
__device__ __forceinline__ void ldsm_x4(u32& r0, u32& r1, u32& r2, u32& r3, u32 addr) {
    asm volatile("ldmatrix.sync.aligned.m8n8.x4.shared.b16 {%0,%1,%2,%3}, [%4];"
                 : "=r"(r0), "=r"(r1), "=r"(r2), "=r"(r3) : "r"(addr));
}
__device__ __forceinline__ void ldsm_x4t(u32& r0, u32& r1, u32& r2, u32& r3, u32 addr) {
    asm volatile("ldmatrix.sync.aligned.m8n8.x4.trans.shared.b16 {%0,%1,%2,%3}, [%4];"
                 : "=r"(r0), "=r"(r1), "=r"(r2), "=r"(r3) : "r"(addr));
}
__device__ __forceinline__ void mma_f16(float c[4], const u32 a[4], u32 b0, u32 b1) {
    asm volatile(
        "mma.sync.aligned.m16n8k16.row.col.f32.f16.f16.f32 "
        "{%0,%1,%2,%3}, {%4,%5,%6,%7}, {%8,%9}, {%0,%1,%2,%3};"
        : "+f"(c[0]), "+f"(c[1]), "+f"(c[2]), "+f"(c[3])
        : "r"(a[0]), "r"(a[1]), "r"(a[2]), "r"(a[3]), "r"(b0), "r"(b1));
}
__device__ __forceinline__ u32 cvt2h(float x, float y) {
    __half2 h = __floats2half2_rn(x, y);
    return *(u32*)&h;
}
__device__ __forceinline__ void split2h(float x, float y, u32& h, u32& l) {
    __half2 hh = __floats2half2_rn(x, y);
    float bx = __low2float(hh), by = __high2float(hh);
    __half2 ll = __floats2half2_rn(x - bx, y - by);
    h = *(u32*)&hh; l = *(u32*)&ll;
}
__device__ __forceinline__ void cvt8f(uint4 v, float f[8]) {
    float2 a0 = __half22float2(*(__half2*)&v.x);
    float2 a1 = __half22float2(*(__half2*)&v.y);
    float2 a2 = __half22float2(*(__half2*)&v.z);
    float2 a3 = __half22float2(*(__half2*)&v.w);
    f[0] = a0.x; f[1] = a0.y; f[2] = a1.x; f[3] = a1.y;
    f[4] = a2.x; f[5] = a2.y; f[6] = a3.x; f[7] = a3.y;
}

// ---------------- init ----------------
__global__ void init_kernel(const float* __restrict__ bm0, const float* __restrict__ bm1) {
    int i = blockIdx.x * blockDim.x + threadIdx.x;
    if (i < NN) { g_cnt[i] = 0; g_fill[i] = 0; }
    if (i < NG * MLP0) g_x0a[i] = bm0[i & (MLP0 - 1)];
    if (i < NG * HH)   g_x0[i] = bm1[i & (HH - 1)];
}

// ---------------- degree histogram ----------------
__global__ void deg_kernel(const int* __restrict__ dst) {
    int e = blockIdx.x * blockDim.x + threadIdx.x;
    if (e < NE) atomicAdd(&g_cnt[dst[e]], 1);
}

// ---------------- exclusive scan (3-phase) ----------------
__global__ void scan1_kernel() {
    __shared__ int sd[1024];
    int t = threadIdx.x;
    int idx = blockIdx.x * 1024 + t;
    int v = (idx < NN) ? g_cnt[idx] : 0;
    sd[t] = v;
    __syncthreads();
    for (int off = 1; off < 1024; off <<= 1) {
        int add = (t >= off) ? sd[t - off] : 0;
        __syncthreads();
        sd[t] += add;
        __syncthreads();
    }
    if (idx < NN) g_rowstart[idx] = sd[t] - v;
    if (t == 1023) g_bsum[blockIdx.x] = sd[t];
}
__global__ void scan2_kernel() {
    __shared__ int sd[128];
    int t = threadIdx.x;
    int v = (t < 98) ? g_bsum[t] : 0;
    sd[t] = v;
    __syncthreads();
    for (int off = 1; off < 128; off <<= 1) {
        int add = (t >= off) ? sd[t - off] : 0;
        __syncthreads();
        sd[t] += add;
        __syncthreads();
    }
    if (t < 98) g_bsum[t] = sd[t] - v;
}
__global__ void scan3_kernel() {
    int idx = blockIdx.x * 1024 + threadIdx.x;
    if (idx < NN) {
        g_rowstart[idx] += g_bsum[blockIdx.x];
        g_dinv[idx] = rsqrtf((float)(g_cnt[idx] + 1));
    }
    if (idx == 0) g_rowstart[NN] = NE;
}

// ---------------- CSR fill ----------------
__global__ void fill_kernel(const int* __restrict__ src, const int* __restrict__ dst) {
    int e = blockIdx.x * blockDim.x + threadIdx.x;
    if (e < NE) {
        int d = dst[e];
        int p = g_rowstart[d] + atomicAdd(&g_fill[d], 1);
        g_srclist[p] = src[e];
    }
}

// ---------------- fp16 MMA GEMM --------------------------------------------------
// C[M,N] (+)= A[M,K] @ B[K,N]. B single fp16.
// AHALF=0: A fp32, split hi+lo fp16 (2-term). AHALF=1: A already fp16 (1-term).
// BM=64, BK=32, double-buffered smem, single-deep reg prefetch.
// 8 warps as 4(wm) x 2(wn); warp tile m16 x (BN/2). MINB: min blocks/SM (reg cap).
#define APAD 40
template<int BN, bool ATOMIC, bool HALF_OUT, bool AHALF, int MINB>
__global__ void __launch_bounds__(256, MINB)
mma_gemm_kernel(const void* __restrict__ Av, int lda,
                const float* __restrict__ B, int ldb,
                float* __restrict__ C, int ldc,
                int M, int K, int kPerSplit)
{
    constexpr int BK    = 32;
    constexpr int WNT   = BN / 2;
    constexpr int NB    = WNT / 16;
    constexpr int BPADT = BN + 8;
    constexpr int BREG  = BN / 32;

    __shared__ __align__(16) u16 sAh[2][64][APAD];
    __shared__ __align__(16) u16 sAl[AHALF ? 1 : 2][AHALF ? 1 : 64][AHALF ? 1 : APAD];
    __shared__ __align__(16) u16 sB [2][32][BPADT];

    const int tid  = threadIdx.x;
    const int lane = tid & 31, wid = tid >> 5;
    const int wm = wid & 3, wn = wid >> 2;
    const int m0 = blockIdx.y * 64;
    const int n0 = blockIdx.x * BN;
    const int k0 = blockIdx.z * kPerSplit;
    const int kend = k0 + kPerSplit;     // exact splits

    const float* Af = (const float*)Av;
    const __half* Ah = (const __half*)Av;
    const int ar0 = tid >> 3, ac = (tid & 7) * 4;
    const int arh = tid >> 2, ach = (tid & 3) * 8;

    float4 aR[2]; uint4 aRh; float4 bR[BREG];
    auto ldg_tile = [&](int kb) {
        if (AHALF) {
            int m = m0 + arh;
            if (m < M) aRh = *(const uint4*)&Ah[(size_t)m * lda + kb + ach];
            else       aRh = make_uint4(0, 0, 0, 0);
        } else {
#pragma unroll
            for (int t = 0; t < 2; t++) {
                int m = m0 + ar0 + 32 * t;
                if (m < M) aR[t] = *(const float4*)&Af[(size_t)m * lda + kb + ac];
                else       aR[t] = make_float4(0.f, 0.f, 0.f, 0.f);
            }
        }
#pragma unroll
        for (int t = 0; t < BREG; t++) {
            int i4 = tid + t * 256;
            int r = i4 / (BN / 4), c4 = i4 % (BN / 4);
            bR[t] = *(const float4*)&B[(size_t)(kb + r) * ldb + n0 + c4 * 4];
        }
    };
    auto sts_tile = [&](int buf) {
        if (AHALF) {
            *(uint4*)&sAh[buf][arh][ach] = aRh;
        } else {
#pragma unroll
            for (int t = 0; t < 2; t++) {
                int r = ar0 + 32 * t;
                u32 h0, h1, l0, l1;
                split2h(aR[t].x, aR[t].y, h0, l0);
                split2h(aR[t].z, aR[t].w, h1, l1);
                *(u64*)&sAh[buf][r][ac] = (u64)h0 | ((u64)h1 << 32);
                *(u64*)&sAl[buf][r][ac] = (u64)l0 | ((u64)l1 << 32);
            }
        }
#pragma unroll
        for (int t = 0; t < BREG; t++) {
            int i4 = tid + t * 256;
            int r = i4 / (BN / 4), c4 = i4 % (BN / 4);
            u32 h0 = cvt2h(bR[t].x, bR[t].y);
            u32 h1 = cvt2h(bR[t].z, bR[t].w);
            *(u64*)&sB[buf][r][c4 * 4] = (u64)h0 | ((u64)h1 << 32);
        }
    };

    const int g = lane >> 3, lr = lane & 7;
    const u32 baseAh = smem_u32(sAh), baseAl = smem_u32(sAl), baseB = smem_u32(sB);
    const u32 offA = (u32)(((16 * wm + lr + 8 * (g & 1)) * APAD + 8 * (g >> 1)) * 2);
    const u32 offB = (u32)(((lr + 8 * (g & 1)) * BPADT + WNT * wn + 8 * (g >> 1)) * 2);
    constexpr u32 ABUF = sizeof(u16) * 64 * APAD;
    constexpr u32 BBUF = sizeof(u16) * 32 * BPADT;

    float c[2 * NB][4];
#pragma unroll
    for (int s = 0; s < 2 * NB; s++)
#pragma unroll
        for (int i = 0; i < 4; i++) c[s][i] = 0.0f;

    ldg_tile(k0);
    sts_tile(0);
    __syncthreads();

    int buf = 0;
    for (int kb = k0; kb < kend; kb += BK) {
        bool has_next = (kb + BK) < kend;
        if (has_next) ldg_tile(kb + BK);

#pragma unroll
        for (int ks = 0; ks < 2; ks++) {
            u32 ah[4], al[4];
            u32 adA = offA + buf * ABUF + ks * 32;
            ldsm_x4(ah[0], ah[1], ah[2], ah[3], baseAh + adA);
            if (!AHALF) ldsm_x4(al[0], al[1], al[2], al[3], baseAl + adA);
#pragma unroll
            for (int nb = 0; nb < NB; nb++) {
                u32 bh[4];
                u32 adB = offB + buf * BBUF + ks * (16 * BPADT * 2) + nb * 32;
                ldsm_x4t(bh[0], bh[1], bh[2], bh[3], baseB + adB);
                mma_f16(c[2 * nb],     ah, bh[0], bh[1]);
                mma_f16(c[2 * nb + 1], ah, bh[2], bh[3]);
                if (!AHALF) {
                    mma_f16(c[2 * nb],     al, bh[0], bh[1]);
                    mma_f16(c[2 * nb + 1], al, bh[2], bh[3]);
                }
            }
        }
        if (has_next) sts_tile(buf ^ 1);
        __syncthreads();
        buf ^= 1;
    }

    // ---- epilogue ----
    const int row = m0 + 16 * wm + (lane >> 2);
    const int colb = n0 + WNT * wn + 2 * (lane & 3);
    __half* Ch = (__half*)C;
#pragma unroll
    for (int rr = 0; rr < 2; rr++) {
        int r = row + 8 * rr;
        if (r >= M) continue;
#pragma unroll
        for (int s = 0; s < 2 * NB; s++) {
            int col = colb + 8 * s;
            if (ATOMIC) {
                atomicAdd(&C[(size_t)r * ldc + col],     c[s][2 * rr]);
                atomicAdd(&C[(size_t)r * ldc + col + 1], c[s][2 * rr + 1]);
            } else if (HALF_OUT) {
                __half2 hv = __floats2half2_rn(c[s][2 * rr], c[s][2 * rr + 1]);
                *(__half2*)&Ch[(size_t)r * ldc + col] = hv;
            } else {
                *(float2*)&C[(size_t)r * ldc + col] =
                    make_float2(c[s][2 * rr], c[s][2 * rr + 1]);
            }
        }
    }
}

// ---------------- gemm3: f32x2 tiles (MLP2 only) ----------------------------------
template<int BM, int BN, int TM, int TN, bool ATOMIC>
__global__ void __launch_bounds__(256)
gemm3_kernel(const float* __restrict__ A, int lda,
             const float* __restrict__ B, int ldb,
             float* __restrict__ C, int ldc,
             int M, int N, int K, int kPerSplit)
{
    constexpr int BK = 16;
    constexpr int AREG = BM * BK / (256 * 4);
    constexpr int BREG = BK * BN / (256 * 4);
    __shared__ float  As[BK][BM + 4];
    __shared__ float4 Bs4[BK][BN / 4];

    const int tid = threadIdx.x;
    const int tx = tid & 15, ty = tid >> 4;
    const int m0 = blockIdx.y * BM;
    const int n0 = blockIdx.x * BN;
    const int k0 = blockIdx.z * kPerSplit;
    int kend = k0 + kPerSplit; if (kend > K) kend = K;

    float4 aR[AREG], bR[BREG];

    auto ldg_tile = [&](int kb) {
#pragma unroll
        for (int t = 0; t < AREG; t++) {
            int i4 = tid + t * 256;
            int r = i4 >> 2, c = (i4 & 3) * 4;
            int m = m0 + r;
            if (m < M) aR[t] = *(const float4*)&A[(size_t)m * lda + kb + c];
            else       aR[t] = make_float4(0.f, 0.f, 0.f, 0.f);
        }
#pragma unroll
        for (int t = 0; t < BREG; t++) {
            int i4 = tid + t * 256;
            int r = i4 / (BN / 4), c4 = i4 % (BN / 4);
            bR[t] = *(const float4*)&B[(size_t)(kb + r) * ldb + n0 + c4 * 4];
        }
    };
    auto sts_tile = [&]() {
#pragma unroll
        for (int t = 0; t < AREG; t++) {
            int i4 = tid + t * 256;
            int r = i4 >> 2, c = (i4 & 3) * 4;
            As[c + 0][r] = aR[t].x; As[c + 1][r] = aR[t].y;
            As[c + 2][r] = aR[t].z; As[c + 3][r] = aR[t].w;
        }
#pragma unroll
        for (int t = 0; t < BREG; t++) {
            int i4 = tid + t * 256;
            Bs4[i4 / (BN / 4)][i4 % (BN / 4)] = bR[t];
        }
    };

    u64 acc[TM][TN / 2];
#pragma unroll
    for (int i = 0; i < TM; i++)
#pragma unroll
        for (int j = 0; j < TN / 2; j++) acc[i][j] = 0ull;

    ldg_tile(k0);
    sts_tile();
    __syncthreads();

    for (int kb = k0; kb < kend; kb += BK) {
        bool has_next = (kb + BK) < kend;
        if (has_next) ldg_tile(kb + BK);

#pragma unroll
        for (int k = 0; k < BK; k++) {
            u64 bp[TN / 2];
#pragma unroll
            for (int j = 0; j < TN / 4; j++) {
                float4 bv = Bs4[k][tx + 16 * j];
                bp[2 * j]     = pack2(bv.x, bv.y);
                bp[2 * j + 1] = pack2(bv.z, bv.w);
            }
            float av[TM];
#pragma unroll
            for (int q = 0; q < TM / 4; q++) {
                float4 a4 = *(const float4*)&As[k][ty * TM + 4 * q];
                av[4 * q + 0] = a4.x; av[4 * q + 1] = a4.y;
                av[4 * q + 2] = a4.z; av[4 * q + 3] = a4.w;
            }
#pragma unroll
            for (int i = 0; i < TM; i++) {
                u64 ap = pack_dup(av[i]);
#pragma unroll
                for (int j = 0; j < TN / 2; j++)
                    acc[i][j] = ffma2(ap, bp[j], acc[i][j]);
            }
        }
        __syncthreads();
        if (has_next) {
            sts_tile();
            __syncthreads();
        }
    }

#pragma unroll
    for (int i = 0; i < TM; i++) {
        int m = m0 + ty * TM + i;
        if (m >= M) continue;
#pragma unroll
        for (int j = 0; j < TN / 4; j++) {
            int col = n0 + tx * 4 + 64 * j;
            float x0, x1, x2, x3;
            unpack2(acc[i][2 * j],     x0, x1);
            unpack2(acc[i][2 * j + 1], x2, x3);
            if (ATOMIC) {
                float* crow = C + (size_t)m * ldc + col;
                atomicAdd(crow + 0, x0);
                atomicAdd(crow + 1, x1);
                atomicAdd(crow + 2, x2);
                atomicAdd(crow + 3, x3);
            } else {
                *(float4*)&C[(size_t)m * ldc + col] = make_float4(x0, x1, x2, x3);
            }
        }
    }
}

// ---- agg1 v3 (fp16 in/out, LDG.128 gather, 4x unrolled independent chains) -------
// warp per node; half-warp per edge slot; 8 edges per iteration (MLP ~4).
__global__ void agg128_kernel(const __half* __restrict__ hp, const float* __restrict__ bias,
                              __half* __restrict__ out) {
    int gw   = (blockIdx.x * blockDim.x + threadIdx.x) >> 5;
    int lane = threadIdx.x & 31;
    if (gw >= NN) return;
    int r0 = g_rowstart[gw], r1 = g_rowstart[gw + 1];
    float dn = g_dinv[gw];
    const int half = lane >> 4, sl = lane & 15;
    const uint4* h16 = (const uint4*)hp;          // 16 uint4 per 128-col row

    float acc[8];
    if (half == 0) {
        float f[8]; cvt8f(h16[(size_t)gw * 16 + sl], f);
#pragma unroll
        for (int i = 0; i < 8; i++) acc[i] = f[i] * dn;
    } else {
#pragma unroll
        for (int i = 0; i < 8; i++) acc[i] = 0.0f;
    }

    for (int eb = r0; eb < r1; eb += 8) {
        int  sarr[4];
#pragma unroll
        for (int t = 0; t < 4; t++) {
            int e0 = eb + half + 2 * t;
            sarr[t] = (e0 < r1) ? g_srclist[e0] : -1;
        }
        float darr[4]; uint4 varr[4];
#pragma unroll
        for (int t = 0; t < 4; t++) {
            if (sarr[t] >= 0) {
                darr[t] = g_dinv[sarr[t]];
                varr[t] = h16[(size_t)sarr[t] * 16 + sl];
            } else {
                darr[t] = 0.0f;
                varr[t] = make_uint4(0, 0, 0, 0);
            }
        }
#pragma unroll
        for (int t = 0; t < 4; t++) {
            float f[8]; cvt8f(varr[t], f);
#pragma unroll
            for (int i = 0; i < 8; i++) acc[i] = fmaf(f[i], darr[t], acc[i]);
        }
    }
#pragma unroll
    for (int i = 0; i < 8; i++)
        acc[i] += __shfl_down_sync(0xFFFFFFFFu, acc[i], 16);

    if (half == 0) {
        float4 b0 = ((const float4*)bias)[2 * sl];
        float4 b1 = ((const float4*)bias)[2 * sl + 1];
        float o[8];
        o[0] = fmaxf(fmaf(acc[0], dn, b0.x), 0.0f);
        o[1] = fmaxf(fmaf(acc[1], dn, b0.y), 0.0f);
        o[2] = fmaxf(fmaf(acc[2], dn, b0.z), 0.0f);
        o[3] = fmaxf(fmaf(acc[3], dn, b0.w), 0.0f);
        o[4] = fmaxf(fmaf(acc[4], dn, b1.x), 0.0f);
        o[5] = fmaxf(fmaf(acc[5], dn, b1.y), 0.0f);
        o[6] = fmaxf(fmaf(acc[6], dn, b1.z), 0.0f);
        o[7] = fmaxf(fmaf(acc[7], dn, b1.w), 0.0f);
        uint4 pv;
        pv.x = cvt2h(o[0], o[1]); pv.y = cvt2h(o[2], o[3]);
        pv.z = cvt2h(o[4], o[5]); pv.w = cvt2h(o[6], o[7]);
        ((uint4*)out)[(size_t)gw * 16 + sl] = pv;
    }
}

// ---- agg2 v3 (fp16 in, fp32 out): quarter-warp per edge slot, 4x unrolled --------
__global__ void agg64_kernel(const __half* __restrict__ hp, const float* __restrict__ bias,
                             float* __restrict__ out) {
    int gw   = (blockIdx.x * blockDim.x + threadIdx.x) >> 5;
    int lane = threadIdx.x & 31;
    if (gw >= NN) return;
    int r0 = g_rowstart[gw], r1 = g_rowstart[gw + 1];
    float dn = g_dinv[gw];
    const int q = lane >> 3, sl = lane & 7;
    const uint4* h8 = (const uint4*)hp;           // 8 uint4 per 64-col row

    float acc[8];
    if (q == 0) {
        float f[8]; cvt8f(h8[(size_t)gw * 8 + sl], f);
#pragma unroll
        for (int i = 0; i < 8; i++) acc[i] = f[i] * dn;
    } else {
#pragma unroll
        for (int i = 0; i < 8; i++) acc[i] = 0.0f;
    }

    for (int eb = r0; eb < r1; eb += 16) {
        int  sarr[4];
#pragma unroll
        for (int t = 0; t < 4; t++) {
            int e0 = eb + q + 4 * t;
            sarr[t] = (e0 < r1) ? g_srclist[e0] : -1;
        }
        float darr[4]; uint4 varr[4];
#pragma unroll
        for (int t = 0; t < 4; t++) {
            if (sarr[t] >= 0) {
                darr[t] = g_dinv[sarr[t]];
                varr[t] = h8[(size_t)sarr[t] * 8 + sl];
            } else {
                darr[t] = 0.0f;
                varr[t] = make_uint4(0, 0, 0, 0);
            }
        }
#pragma unroll
        for (int t = 0; t < 4; t++) {
            float f[8]; cvt8f(varr[t], f);
#pragma unroll
            for (int i = 0; i < 8; i++) acc[i] = fmaf(f[i], darr[t], acc[i]);
        }
    }
#pragma unroll
    for (int i = 0; i < 8; i++) {
        acc[i] += __shfl_down_sync(0xFFFFFFFFu, acc[i], 16);
        acc[i] += __shfl_down_sync(0xFFFFFFFFu, acc[i], 8);
    }

    if (q == 0) {
        float4 b0 = ((const float4*)bias)[2 * sl];
        float4 b1 = ((const float4*)bias)[2 * sl + 1];
        float4 o0, o1;
        o0.x = fmaxf(fmaf(acc[0], dn, b0.x), 0.0f);
        o0.y = fmaxf(fmaf(acc[1], dn, b0.y), 0.0f);
        o0.z = fmaxf(fmaf(acc[2], dn, b0.z), 0.0f);
        o0.w = fmaxf(fmaf(acc[3], dn, b0.w), 0.0f);
        o1.x = fmaxf(fmaf(acc[4], dn, b1.x), 0.0f);
        o1.y = fmaxf(fmaf(acc[5], dn, b1.y), 0.0f);
        o1.z = fmaxf(fmaf(acc[6], dn, b1.z), 0.0f);
        o1.w = fmaxf(fmaf(acc[7], dn, b1.w), 0.0f);
        ((float4*)out)[(size_t)gw * 16 + 2 * sl]     = o0;
        ((float4*)out)[(size_t)gw * 16 + 2 * sl + 1] = o1;
    }
}

// ---------------- per-graph node ranges (batch is sorted) ----------------
__global__ void gstart_kernel(const int* __restrict__ batch) {
    int g = threadIdx.x;
    if (g > NG) return;
    int lo = 0, hi = NN;
    while (lo < hi) { int mid = (lo + hi) >> 1; if (batch[mid] < g) lo = mid + 1; else hi = mid; }
    g_gstart[g] = lo;
}

// ---------------- global_add_pool (atomic-free, block per graph) ----------------
__global__ void pool_kernel() {
    __shared__ float sm[4][HH];
    int b   = blockIdx.x;
    int f   = threadIdx.x & 63;
    int sub = threadIdx.x >> 6;
    int n0  = g_gstart[b], n1 = g_gstart[b + 1];
    float acc = 0.0f;
    for (int node = n0 + sub; node < n1; node += 4)
        acc += g_a2[(size_t)node * HH + f];
    sm[sub][f] = acc;
    __syncthreads();
    if (sub == 0)
        g_pool[b * HH + f] = sm[0][f] + sm[1][f] + sm[2][f] + sm[3][f];
}

// ---------------- head: Wmx + concat + Wfc + log_softmax ----------------
__global__ void final_kernel(const float* __restrict__ Wmx, const float* __restrict__ bmx,
                             const float* __restrict__ Wfc, const float* __restrict__ bfc,
                             float* __restrict__ out) {
    int b = blockIdx.x;
    int t = threadIdx.x;
    __shared__ float xt[2 * HH];
    __shared__ float pr[HH];
    __shared__ float lg[NC];
    __shared__ float s_lse;
    pr[t] = g_pool[b * HH + t];
    xt[t] = g_x0[b * HH + t];
    __syncthreads();
    float acc = bmx[t];
    for (int k = 0; k < HH; k++) acc = fmaf(pr[k], Wmx[k * HH + t], acc);
    xt[HH + t] = acc;
    __syncthreads();
    if (t < NC) {
        float l = bfc[t];
        for (int k = 0; k < 2 * HH; k++) l = fmaf(xt[k], Wfc[k * NC + t], l);
        lg[t] = l;
    }
    __syncthreads();
    if (t == 0) {
        float m = -1e30f;
        for (int j = 0; j < NC; j++) m = fmaxf(m, lg[j]);
        float s = 0.0f;
        for (int j = 0; j < NC; j++) s += expf(lg[j] - m);
        s_lse = m + logf(s);
    }
    __syncthreads();
    if (t < NC) out[b * NC + t] = lg[t] - s_lse;
}

// ---------------- launch (multi-stream fork/join inside graph capture) ----------------
extern "C" void kernel_launch(void* const* d_in, const int* in_sizes, int n_in,
                              void* d_out, int out_size) {
    const float* x    = (const float*)d_in[0];
    const int*   ei   = (const int*)  d_in[1];
    const float* img  = (const float*)d_in[2];
    const int*   batch= (const int*)  d_in[3];
    const float* W1   = (const float*)d_in[4];
    const float* b1   = (const float*)d_in[5];
    const float* W2   = (const float*)d_in[6];
    const float* b2   = (const float*)d_in[7];
    const float* Wm0  = (const float*)d_in[8];
    const float* bm0  = (const float*)d_in[9];
    const float* Wm1  = (const float*)d_in[10];
    const float* bm1  = (const float*)d_in[11];
    const float* Wmx  = (const float*)d_in[12];
    const float* bmx  = (const float*)d_in[13];
    const float* Wfc  = (const float*)d_in[14];
    const float* bfc  = (const float*)d_in[15];
    float* out = (float*)d_out;
    const int* src = ei;
    const int* dst = ei + NE;

    __half *p_hp1h, *p_hp2h, *p_a1h;
    float *p_a2, *p_x0a, *p_x0;
    cudaGetSymbolAddress((void**)&p_hp1h, g_hp1h);
    cudaGetSymbolAddress((void**)&p_a1h,  g_a1h);
    cudaGetSymbolAddress((void**)&p_hp2h, g_hp2h);
    cudaGetSymbolAddress((void**)&p_a2,   g_a2);
    cudaGetSymbolAddress((void**)&p_x0a,  g_x0a);
    cudaGetSymbolAddress((void**)&p_x0,   g_x0);

    static cudaStream_t s1 = nullptr, s2 = nullptr;
    static cudaEvent_t evF = nullptr, ev1 = nullptr, ev2 = nullptr;
    if (!s1) {
        cudaStreamCreateWithFlags(&s1, cudaStreamNonBlocking);
        cudaStreamCreateWithFlags(&s2, cudaStreamNonBlocking);
        cudaEventCreateWithFlags(&evF, cudaEventDisableTiming);
        cudaEventCreateWithFlags(&ev1, cudaEventDisableTiming);
        cudaEventCreateWithFlags(&ev2, cudaEventDisableTiming);
    }

    // --- main stream: init, then fork ---
    init_kernel<<<(NN + 255) / 256, 256>>>(bm0, bm1);            // 1
    cudaEventRecord(evF, 0);
    cudaStreamWaitEvent(s1, evF, 0);
    cudaStreamWaitEvent(s2, evF, 0);

    deg_kernel <<<(NE + 255) / 256, 256>>>(dst);                 // 2 (main)
    scan1_kernel<<<98, 1024>>>();                                // 3 (main)

    // 4th submission = fp16 tensor-core image GEMM
    // x0a(=bm0) += img @ Wm0   [64,50176]@[50176,1024], split-K 56x896, 3 CTA/SM
    {
        dim3 grid(MLP0 / 128, 1, 56);
        mma_gemm_kernel<128, true, false, false, 3><<<grid, 256, 0, s2>>>(
            img, IMGF, Wm0, MLP0, p_x0a, MLP0, NG, IMGF, 896);
    }

    // stream s1: transform1 via fp16 MMA, fp16 out: hp1 = x @ W1
    {
        dim3 grid(1, (NN + 63) / 64, 1);
        mma_gemm_kernel<128, false, true, false, 1><<<grid, 256, 0, s1>>>(
            x, FIN, W1, H2, (float*)p_hp1h, H2, NN, FIN, FIN);
    }
    gstart_kernel<<<1, NG + 1, 0, s1>>>(batch);
    cudaEventRecord(ev1, s1);

    // main: finish CSR
    scan2_kernel<<<1, 128>>>();
    scan3_kernel<<<98, 1024>>>();
    fill_kernel<<<(NE + 255) / 256, 256>>>(src, dst);

    // s2: x0(=bm1) += x0a @ Wm1   [64,1024]@[1024,64], split-K 16
    {
        dim3 grid(1, 1, 16);
        gemm3_kernel<64, 64, 4, 4, true><<<grid, 256, 0, s2>>>(
            p_x0a, MLP0, Wm1, HH, p_x0, HH, NG, HH, MLP0, MLP0 / 16);
    }
    cudaEventRecord(ev2, s2);

    // join s1 into main, then conv chain
    cudaStreamWaitEvent(0, ev1, 0);
    agg128_kernel<<<(NN * 32 + 255) / 256, 256>>>(p_hp1h, b1, p_a1h);

    // transform2 via fp16 MMA (BN=64, fp16 A, fp16 out): hp2 = a1 @ W2
    {
        dim3 grid(1, (NN + 63) / 64, 1);
        mma_gemm_kernel<64, false, true, true, 1><<<grid, 256>>>(
            p_a1h, H2, W2, HH, (float*)p_hp2h, HH, NN, H2, H2);
    }
    agg64_kernel<<<(NN * 32 + 255) / 256, 256>>>(p_hp2h, b2, p_a2);
    pool_kernel<<<NG, 256>>>();

    // join s2 into main, then head
    cudaStreamWaitEvent(0, ev2, 0);
    final_kernel<<<NG, HH>>>(Wmx, bmx, Wfc, bfc, out);
}

// round 16
// speedup vs baseline: 1.0296x; 1.0284x over previous
#include <cuda_runtime.h>
#include <cuda_bf16.h>
#include <cuda_fp16.h>

#define NN    100000
#define NE    1600000
#define NG    64
#define FIN   128
#define HH    64
#define H2    128
#define IMGF  50176
#define MLP0  1024
#define NC    38

typedef unsigned long long u64;
typedef unsigned int u32;
typedef unsigned short u16;

// ---------------- scratch (device globals; no allocation allowed) ----------------
__device__ __align__(16) __half g_hp1h[(size_t)NN * H2];   // dinv-scaled transform1 (fp16)
__device__ __align__(16) __half g_a1h [(size_t)NN * H2];   // conv1 out (fp16)
__device__ __align__(16) __half g_hp2h[(size_t)NN * HH];   // dinv-scaled transform2 (fp16)
__device__ __align__(16) float  g_a2 [(size_t)NN * HH];    // conv2 out (fp32)
__device__ int   g_cnt[NN];
__device__ int   g_fill[NN];         // working slot counters (seeded = rowstart)
__device__ int   g_rowstart[NN + 1];
__device__ int   g_srclist[NE];
__device__ float g_dinv[NN];
__device__ int   g_bsum[128];
__device__ int   g_gstart[NG + 1];
__device__ float g_x0a[NG * MLP0];
__device__ float g_x0 [NG * HH];

// ---------------- packed f32x2 helpers ----------------
__device__ __forceinline__ u64 pack_dup(float a) {
    u64 r; asm("mov.b64 %0, {%1, %1};" : "=l"(r) : "f"(a)); return r;
}
__device__ __forceinline__ u64 pack2(float lo, float hi) {
    u64 r; asm("mov.b64 %0, {%1, %2};" : "=l"(r) : "f"(lo), "f"(hi)); return r;
}
__device__ __forceinline__ u64 ffma2(u64 a, u64 b, u64 c) {
    u64 d; asm("fma.rn.f32x2 %0, %1, %2, %3;" : "=l"(d) : "l"(a), "l"(b), "l"(c)); return d;
}
__device__ __forceinline__ void unpack2(u64 v, float& lo, float& hi) {
    asm("mov.b64 {%0, %1}, %2;" : "=f"(lo), "=f"(hi) : "l"(v));
}

// ---------------- mma / ldmatrix helpers (fp16 path) ----------------
__device__ __forceinline__ u32 smem_u32(const void* p) {
    u32 a;
    asm("{ .reg .u64 t; cvta.to.shared.u64 t, %1; cvt.u32.u64 %0, t; }" : "=r"(a) : "l"(p));
    return a;
}
__device__ __forceinline__ void ldsm_x4(u32& r0, u32& r1, u32& r2, u32& r3, u32 addr) {
    asm volatile("ldmatrix.sync.aligned.m8n8.x4.shared.b16 {%0,%1,%2,%3}, [%4];"
                 : "=r"(r0), "=r"(r1), "=r"(r2), "=r"(r3) : "r"(addr));
}
__device__ __forceinline__ void ldsm_x4t(u32& r0, u32& r1, u32& r2, u32& r3, u32 addr) {
    asm volatile("ldmatrix.sync.aligned.m8n8.x4.trans.shared.b16 {%0,%1,%2,%3}, [%4];"
                 : "=r"(r0), "=r"(r1), "=r"(r2), "=r"(r3) : "r"(addr));
}
__device__ __forceinline__ void mma_f16(float c[4], const u32 a[4], u32 b0, u32 b1) {
    asm volatile(
        "mma.sync.aligned.m16n8k16.row.col.f32.f16.f16.f32 "
        "{%0,%1,%2,%3}, {%4,%5,%6,%7}, {%8,%9}, {%0,%1,%2,%3};"
        : "+f"(c[0]), "+f"(c[1]), "+f"(c[2]), "+f"(c[3])
        : "r"(a[0]), "r"(a[1]), "r"(a[2]), "r"(a[3]), "r"(b0), "r"(b1));
}
__device__ __forceinline__ u32 cvt2h(float x, float y) {
    __half2 h = __floats2half2_rn(x, y);
    return *(u32*)&h;
}
__device__ __forceinline__ void split2h(float x, float y, u32& h, u32& l) {
    __half2 hh = __floats2half2_rn(x, y);
    float bx = __low2float(hh), by = __high2float(hh);
    __half2 ll = __floats2half2_rn(x - bx, y - by);
    h = *(u32*)&hh; l = *(u32*)&ll;
}
__device__ __forceinline__ void cvt8f(uint4 v, float f[8]) {
    float2 a0 = __half22float2(*(__half2*)&v.x);
    float2 a1 = __half22float2(*(__half2*)&v.y);
    float2 a2 = __half22float2(*(__half2*)&v.z);
    float2 a3 = __half22float2(*(__half2*)&v.w);
    f[0] = a0.x; f[1] = a0.y; f[2] = a1.x; f[3] = a1.y;
    f[4] = a2.x; f[5] = a2.y; f[6] = a3.x; f[7] = a3.y;
}

// ---------------- init ----------------
__global__ void init_kernel(const float* __restrict__ bm0, const float* __restrict__ bm1) {
    int i = blockIdx.x * blockDim.x + threadIdx.x;
    if (i < NN) g_cnt[i] = 0;
    if (i < NG * MLP0) g_x0a[i] = bm0[i & (MLP0 - 1)];
    if (i < NG * HH)   g_x0[i] = bm1[i & (HH - 1)];
}

// ---------------- degree histogram ----------------
__global__ void deg_kernel(const int* __restrict__ dst) {
    int e = blockIdx.x * blockDim.x + threadIdx.x;
    if (e < NE) atomicAdd(&g_cnt[dst[e]], 1);
}

// ---------------- exclusive scan (3-phase) ----------------
__global__ void scan1_kernel() {
    __shared__ int sd[1024];
    int t = threadIdx.x;
    int idx = blockIdx.x * 1024 + t;
    int v = (idx < NN) ? g_cnt[idx] : 0;
    sd[t] = v;
    __syncthreads();
    for (int off = 1; off < 1024; off <<= 1) {
        int add = (t >= off) ? sd[t - off] : 0;
        __syncthreads();
        sd[t] += add;
        __syncthreads();
    }
    if (idx < NN) g_rowstart[idx] = sd[t] - v;
    if (t == 1023) g_bsum[blockIdx.x] = sd[t];
}
__global__ void scan2_kernel() {
    __shared__ int sd[128];
    int t = threadIdx.x;
    int v = (t < 98) ? g_bsum[t] : 0;
    sd[t] = v;
    __syncthreads();
    for (int off = 1; off < 128; off <<= 1) {
        int add = (t >= off) ? sd[t - off] : 0;
        __syncthreads();
        sd[t] += add;
        __syncthreads();
    }
    if (t < 98) g_bsum[t] = sd[t] - v;
}
__global__ void scan3_kernel() {
    int idx = blockIdx.x * 1024 + threadIdx.x;
    if (idx < NN) {
        int rs = g_rowstart[idx] + g_bsum[blockIdx.x];
        g_rowstart[idx] = rs;
        g_fill[idx] = rs;                       // working slot counter
        g_dinv[idx] = rsqrtf((float)(g_cnt[idx] + 1));
    }
    if (idx == 0) g_rowstart[NN] = NE;
}

// ---------------- CSR fill (single atomic per edge) ----------------
__global__ void fill_kernel(const int* __restrict__ src, const int* __restrict__ dst) {
    int e = blockIdx.x * blockDim.x + threadIdx.x;
    if (e < NE) {
        int p = atomicAdd(&g_fill[dst[e]], 1);
        g_srclist[p] = src[e];
    }
}

// ---------------- fp16 MMA GEMM --------------------------------------------------
// C[M,N] (+)= A[M,K] @ B[K,N]. B single fp16.
// AHALF=0: A fp32, split hi+lo fp16 (2-term). AHALF=1: A already fp16 (1-term).
// RSCALE: scale row m of the output by rowscale[m] (fused dinv).
#define APAD 40
template<int BN, bool ATOMIC, bool HALF_OUT, bool AHALF, bool RSCALE, int MINB>
__global__ void __launch_bounds__(256, MINB)
mma_gemm_kernel(const void* __restrict__ Av, int lda,
                const float* __restrict__ B, int ldb,
                float* __restrict__ C, int ldc,
                int M, int K, int kPerSplit,
                const float* __restrict__ rowscale)
{
    constexpr int BK    = 32;
    constexpr int WNT   = BN / 2;
    constexpr int NB    = WNT / 16;
    constexpr int BPADT = BN + 8;
    constexpr int BREG  = BN / 32;

    __shared__ __align__(16) u16 sAh[2][64][APAD];
    __shared__ __align__(16) u16 sAl[AHALF ? 1 : 2][AHALF ? 1 : 64][AHALF ? 1 : APAD];
    __shared__ __align__(16) u16 sB [2][32][BPADT];

    const int tid  = threadIdx.x;
    const int lane = tid & 31, wid = tid >> 5;
    const int wm = wid & 3, wn = wid >> 2;
    const int m0 = blockIdx.y * 64;
    const int n0 = blockIdx.x * BN;
    const int k0 = blockIdx.z * kPerSplit;
    const int kend = k0 + kPerSplit;     // exact splits

    const float* Af = (const float*)Av;
    const __half* Ah = (const __half*)Av;
    const int ar0 = tid >> 3, ac = (tid & 7) * 4;
    const int arh = tid >> 2, ach = (tid & 3) * 8;

    float4 aR[2]; uint4 aRh; float4 bR[BREG];
    auto ldg_tile = [&](int kb) {
        if (AHALF) {
            int m = m0 + arh;
            if (m < M) aRh = *(const uint4*)&Ah[(size_t)m * lda + kb + ach];
            else       aRh = make_uint4(0, 0, 0, 0);
        } else {
#pragma unroll
            for (int t = 0; t < 2; t++) {
                int m = m0 + ar0 + 32 * t;
                if (m < M) aR[t] = *(const float4*)&Af[(size_t)m * lda + kb + ac];
                else       aR[t] = make_float4(0.f, 0.f, 0.f, 0.f);
            }
        }
#pragma unroll
        for (int t = 0; t < BREG; t++) {
            int i4 = tid + t * 256;
            int r = i4 / (BN / 4), c4 = i4 % (BN / 4);
            bR[t] = *(const float4*)&B[(size_t)(kb + r) * ldb + n0 + c4 * 4];
        }
    };
    auto sts_tile = [&](int buf) {
        if (AHALF) {
            *(uint4*)&sAh[buf][arh][ach] = aRh;
        } else {
#pragma unroll
            for (int t = 0; t < 2; t++) {
                int r = ar0 + 32 * t;
                u32 h0, h1, l0, l1;
                split2h(aR[t].x, aR[t].y, h0, l0);
                split2h(aR[t].z, aR[t].w, h1, l1);
                *(u64*)&sAh[buf][r][ac] = (u64)h0 | ((u64)h1 << 32);
                *(u64*)&sAl[buf][r][ac] = (u64)l0 | ((u64)l1 << 32);
            }
        }
#pragma unroll
        for (int t = 0; t < BREG; t++) {
            int i4 = tid + t * 256;
            int r = i4 / (BN / 4), c4 = i4 % (BN / 4);
            u32 h0 = cvt2h(bR[t].x, bR[t].y);
            u32 h1 = cvt2h(bR[t].z, bR[t].w);
            *(u64*)&sB[buf][r][c4 * 4] = (u64)h0 | ((u64)h1 << 32);
        }
    };

    const int g = lane >> 3, lr = lane & 7;
    const u32 baseAh = smem_u32(sAh), baseAl = smem_u32(sAl), baseB = smem_u32(sB);
    const u32 offA = (u32)(((16 * wm + lr + 8 * (g & 1)) * APAD + 8 * (g >> 1)) * 2);
    const u32 offB = (u32)(((lr + 8 * (g & 1)) * BPADT + WNT * wn + 8 * (g >> 1)) * 2);
    constexpr u32 ABUF = sizeof(u16) * 64 * APAD;
    constexpr u32 BBUF = sizeof(u16) * 32 * BPADT;

    float c[2 * NB][4];
#pragma unroll
    for (int s = 0; s < 2 * NB; s++)
#pragma unroll
        for (int i = 0; i < 4; i++) c[s][i] = 0.0f;

    ldg_tile(k0);
    sts_tile(0);
    __syncthreads();

    int buf = 0;
    for (int kb = k0; kb < kend; kb += BK) {
        bool has_next = (kb + BK) < kend;
        if (has_next) ldg_tile(kb + BK);

#pragma unroll
        for (int ks = 0; ks < 2; ks++) {
            u32 ah[4], al[4];
            u32 adA = offA + buf * ABUF + ks * 32;
            ldsm_x4(ah[0], ah[1], ah[2], ah[3], baseAh + adA);
            if (!AHALF) ldsm_x4(al[0], al[1], al[2], al[3], baseAl + adA);
#pragma unroll
            for (int nb = 0; nb < NB; nb++) {
                u32 bh[4];
                u32 adB = offB + buf * BBUF + ks * (16 * BPADT * 2) + nb * 32;
                ldsm_x4t(bh[0], bh[1], bh[2], bh[3], baseB + adB);
                mma_f16(c[2 * nb],     ah, bh[0], bh[1]);
                mma_f16(c[2 * nb + 1], ah, bh[2], bh[3]);
                if (!AHALF) {
                    mma_f16(c[2 * nb],     al, bh[0], bh[1]);
                    mma_f16(c[2 * nb + 1], al, bh[2], bh[3]);
                }
            }
        }
        if (has_next) sts_tile(buf ^ 1);
        __syncthreads();
        buf ^= 1;
    }

    // ---- epilogue ----
    const int row = m0 + 16 * wm + (lane >> 2);
    const int colb = n0 + WNT * wn + 2 * (lane & 3);
    __half* Ch = (__half*)C;
#pragma unroll
    for (int rr = 0; rr < 2; rr++) {
        int r = row + 8 * rr;
        if (r >= M) continue;
        float sc = RSCALE ? rowscale[r] : 1.0f;
#pragma unroll
        for (int s = 0; s < 2 * NB; s++) {
            int col = colb + 8 * s;
            if (ATOMIC) {
                atomicAdd(&C[(size_t)r * ldc + col],     c[s][2 * rr]);
                atomicAdd(&C[(size_t)r * ldc + col + 1], c[s][2 * rr + 1]);
            } else if (HALF_OUT) {
                __half2 hv = __floats2half2_rn(c[s][2 * rr] * sc, c[s][2 * rr + 1] * sc);
                *(__half2*)&Ch[(size_t)r * ldc + col] = hv;
            } else {
                *(float2*)&C[(size_t)r * ldc + col] =
                    make_float2(c[s][2 * rr], c[s][2 * rr + 1]);
            }
        }
    }
}

// ---------------- gemm3: f32x2 tiles (MLP2 only) ----------------------------------
template<int BM, int BN, int TM, int TN, bool ATOMIC>
__global__ void __launch_bounds__(256)
gemm3_kernel(const float* __restrict__ A, int lda,
             const float* __restrict__ B, int ldb,
             float* __restrict__ C, int ldc,
             int M, int N, int K, int kPerSplit)
{
    constexpr int BK = 16;
    constexpr int AREG = BM * BK / (256 * 4);
    constexpr int BREG = BK * BN / (256 * 4);
    __shared__ float  As[BK][BM + 4];
    __shared__ float4 Bs4[BK][BN / 4];

    const int tid = threadIdx.x;
    const int tx = tid & 15, ty = tid >> 4;
    const int m0 = blockIdx.y * BM;
    const int n0 = blockIdx.x * BN;
    const int k0 = blockIdx.z * kPerSplit;
    int kend = k0 + kPerSplit; if (kend > K) kend = K;

    float4 aR[AREG], bR[BREG];

    auto ldg_tile = [&](int kb) {
#pragma unroll
        for (int t = 0; t < AREG; t++) {
            int i4 = tid + t * 256;
            int r = i4 >> 2, c = (i4 & 3) * 4;
            int m = m0 + r;
            if (m < M) aR[t] = *(const float4*)&A[(size_t)m * lda + kb + c];
            else       aR[t] = make_float4(0.f, 0.f, 0.f, 0.f);
        }
#pragma unroll
        for (int t = 0; t < BREG; t++) {
            int i4 = tid + t * 256;
            int r = i4 / (BN / 4), c4 = i4 % (BN / 4);
            bR[t] = *(const float4*)&B[(size_t)(kb + r) * ldb + n0 + c4 * 4];
        }
    };
    auto sts_tile = [&]() {
#pragma unroll
        for (int t = 0; t < AREG; t++) {
            int i4 = tid + t * 256;
            int r = i4 >> 2, c = (i4 & 3) * 4;
            As[c + 0][r] = aR[t].x; As[c + 1][r] = aR[t].y;
            As[c + 2][r] = aR[t].z; As[c + 3][r] = aR[t].w;
        }
#pragma unroll
        for (int t = 0; t < BREG; t++) {
            int i4 = tid + t * 256;
            Bs4[i4 / (BN / 4)][i4 % (BN / 4)] = bR[t];
        }
    };

    u64 acc[TM][TN / 2];
#pragma unroll
    for (int i = 0; i < TM; i++)
#pragma unroll
        for (int j = 0; j < TN / 2; j++) acc[i][j] = 0ull;

    ldg_tile(k0);
    sts_tile();
    __syncthreads();

    for (int kb = k0; kb < kend; kb += BK) {
        bool has_next = (kb + BK) < kend;
        if (has_next) ldg_tile(kb + BK);

#pragma unroll
        for (int k = 0; k < BK; k++) {
            u64 bp[TN / 2];
#pragma unroll
            for (int j = 0; j < TN / 4; j++) {
                float4 bv = Bs4[k][tx + 16 * j];
                bp[2 * j]     = pack2(bv.x, bv.y);
                bp[2 * j + 1] = pack2(bv.z, bv.w);
            }
            float av[TM];
#pragma unroll
            for (int q = 0; q < TM / 4; q++) {
                float4 a4 = *(const float4*)&As[k][ty * TM + 4 * q];
                av[4 * q + 0] = a4.x; av[4 * q + 1] = a4.y;
                av[4 * q + 2] = a4.z; av[4 * q + 3] = a4.w;
            }
#pragma unroll
            for (int i = 0; i < TM; i++) {
                u64 ap = pack_dup(av[i]);
#pragma unroll
                for (int j = 0; j < TN / 2; j++)
                    acc[i][j] = ffma2(ap, bp[j], acc[i][j]);
            }
        }
        __syncthreads();
        if (has_next) {
            sts_tile();
            __syncthreads();
        }
    }

#pragma unroll
    for (int i = 0; i < TM; i++) {
        int m = m0 + ty * TM + i;
        if (m >= M) continue;
#pragma unroll
        for (int j = 0; j < TN / 4; j++) {
            int col = n0 + tx * 4 + 64 * j;
            float x0, x1, x2, x3;
            unpack2(acc[i][2 * j],     x0, x1);
            unpack2(acc[i][2 * j + 1], x2, x3);
            if (ATOMIC) {
                float* crow = C + (size_t)m * ldc + col;
                atomicAdd(crow + 0, x0);
                atomicAdd(crow + 1, x1);
                atomicAdd(crow + 2, x2);
                atomicAdd(crow + 3, x3);
            } else {
                *(float4*)&C[(size_t)m * ldc + col] = make_float4(x0, x1, x2, x3);
            }
        }
    }
}

// ---- agg1 v4 (pre-scaled fp16 features, no per-edge dinv) ------------------------
// out[d] = relu(dinv_d * (sum_s hp'_s + hp'_d) + b),  hp' = dinv * hp (fused in GEMM)
__global__ void agg128_kernel(const __half* __restrict__ hp, const float* __restrict__ bias,
                              __half* __restrict__ out) {
    int gw   = (blockIdx.x * blockDim.x + threadIdx.x) >> 5;
    int lane = threadIdx.x & 31;
    if (gw >= NN) return;
    int r0 = g_rowstart[gw], r1 = g_rowstart[gw + 1];
    float dn = g_dinv[gw];
    const int half = lane >> 4, sl = lane & 15;
    const uint4* h16 = (const uint4*)hp;

    float acc[8];
    if (half == 0) {
        float f[8]; cvt8f(h16[(size_t)gw * 16 + sl], f);
#pragma unroll
        for (int i = 0; i < 8; i++) acc[i] = f[i];
    } else {
#pragma unroll
        for (int i = 0; i < 8; i++) acc[i] = 0.0f;
    }

    for (int eb = r0; eb < r1; eb += 8) {
        int sarr[4];
#pragma unroll
        for (int t = 0; t < 4; t++) {
            int e0 = eb + half + 2 * t;
            sarr[t] = (e0 < r1) ? g_srclist[e0] : -1;
        }
        uint4 varr[4];
#pragma unroll
        for (int t = 0; t < 4; t++)
            varr[t] = (sarr[t] >= 0) ? h16[(size_t)sarr[t] * 16 + sl]
                                     : make_uint4(0, 0, 0, 0);
#pragma unroll
        for (int t = 0; t < 4; t++) {
            float f[8]; cvt8f(varr[t], f);
#pragma unroll
            for (int i = 0; i < 8; i++) acc[i] += f[i];
        }
    }
#pragma unroll
    for (int i = 0; i < 8; i++)
        acc[i] += __shfl_down_sync(0xFFFFFFFFu, acc[i], 16);

    if (half == 0) {
        float4 b0 = ((const float4*)bias)[2 * sl];
        float4 b1 = ((const float4*)bias)[2 * sl + 1];
        float o[8];
        o[0] = fmaxf(fmaf(acc[0], dn, b0.x), 0.0f);
        o[1] = fmaxf(fmaf(acc[1], dn, b0.y), 0.0f);
        o[2] = fmaxf(fmaf(acc[2], dn, b0.z), 0.0f);
        o[3] = fmaxf(fmaf(acc[3], dn, b0.w), 0.0f);
        o[4] = fmaxf(fmaf(acc[4], dn, b1.x), 0.0f);
        o[5] = fmaxf(fmaf(acc[5], dn, b1.y), 0.0f);
        o[6] = fmaxf(fmaf(acc[6], dn, b1.z), 0.0f);
        o[7] = fmaxf(fmaf(acc[7], dn, b1.w), 0.0f);
        uint4 pv;
        pv.x = cvt2h(o[0], o[1]); pv.y = cvt2h(o[2], o[3]);
        pv.z = cvt2h(o[4], o[5]); pv.w = cvt2h(o[6], o[7]);
        ((uint4*)out)[(size_t)gw * 16 + sl] = pv;
    }
}

// ---- agg2 v4 (pre-scaled fp16 features, fp32 out) --------------------------------
__global__ void agg64_kernel(const __half* __restrict__ hp, const float* __restrict__ bias,
                             float* __restrict__ out) {
    int gw   = (blockIdx.x * blockDim.x + threadIdx.x) >> 5;
    int lane = threadIdx.x & 31;
    if (gw >= NN) return;
    int r0 = g_rowstart[gw], r1 = g_rowstart[gw + 1];
    float dn = g_dinv[gw];
    const int q = lane >> 3, sl = lane & 7;
    const uint4* h8 = (const uint4*)hp;

    float acc[8];
    if (q == 0) {
        float f[8]; cvt8f(h8[(size_t)gw * 8 + sl], f);
#pragma unroll
        for (int i = 0; i < 8; i++) acc[i] = f[i];
    } else {
#pragma unroll
        for (int i = 0; i < 8; i++) acc[i] = 0.0f;
    }

    for (int eb = r0; eb < r1; eb += 16) {
        int sarr[4];
#pragma unroll
        for (int t = 0; t < 4; t++) {
            int e0 = eb + q + 4 * t;
            sarr[t] = (e0 < r1) ? g_srclist[e0] : -1;
        }
        uint4 varr[4];
#pragma unroll
        for (int t = 0; t < 4; t++)
            varr[t] = (sarr[t] >= 0) ? h8[(size_t)sarr[t] * 8 + sl]
                                     : make_uint4(0, 0, 0, 0);
#pragma unroll
        for (int t = 0; t < 4; t++) {
            float f[8]; cvt8f(varr[t], f);
#pragma unroll
            for (int i = 0; i < 8; i++) acc[i] += f[i];
        }
    }
#pragma unroll
    for (int i = 0; i < 8; i++) {
        acc[i] += __shfl_down_sync(0xFFFFFFFFu, acc[i], 16);
        acc[i] += __shfl_down_sync(0xFFFFFFFFu, acc[i], 8);
    }

    if (q == 0) {
        float4 b0 = ((const float4*)bias)[2 * sl];
        float4 b1 = ((const float4*)bias)[2 * sl + 1];
        float4 o0, o1;
        o0.x = fmaxf(fmaf(acc[0], dn, b0.x), 0.0f);
        o0.y = fmaxf(fmaf(acc[1], dn, b0.y), 0.0f);
        o0.z = fmaxf(fmaf(acc[2], dn, b0.z), 0.0f);
        o0.w = fmaxf(fmaf(acc[3], dn, b0.w), 0.0f);
        o1.x = fmaxf(fmaf(acc[4], dn, b1.x), 0.0f);
        o1.y = fmaxf(fmaf(acc[5], dn, b1.y), 0.0f);
        o1.z = fmaxf(fmaf(acc[6], dn, b1.z), 0.0f);
        o1.w = fmaxf(fmaf(acc[7], dn, b1.w), 0.0f);
        ((float4*)out)[(size_t)gw * 16 + 2 * sl]     = o0;
        ((float4*)out)[(size_t)gw * 16 + 2 * sl + 1] = o1;
    }
}

// ---------------- per-graph node ranges (batch is sorted) ----------------
__global__ void gstart_kernel(const int* __restrict__ batch) {
    int g = threadIdx.x;
    if (g > NG) return;
    int lo = 0, hi = NN;
    while (lo < hi) { int mid = (lo + hi) >> 1; if (batch[mid] < g) lo = mid + 1; else hi = mid; }
    g_gstart[g] = lo;
}

// ---------------- fused pool + head (256 threads per graph) ----------------
__global__ void final_kernel(const float* __restrict__ Wmx, const float* __restrict__ bmx,
                             const float* __restrict__ Wfc, const float* __restrict__ bfc,
                             float* __restrict__ out) {
    __shared__ float sm[4][HH];
    __shared__ float pr[HH];
    __shared__ float xt[2 * HH];
    __shared__ float lg[NC];
    __shared__ float s_lse;
    int b = blockIdx.x;
    int t = threadIdx.x;
    int f = t & 63, sub = t >> 6;

    // pool
    int n0 = g_gstart[b], n1 = g_gstart[b + 1];
    float acc = 0.0f;
    for (int node = n0 + sub; node < n1; node += 4)
        acc += g_a2[(size_t)node * HH + f];
    sm[sub][f] = acc;
    __syncthreads();

    if (t < HH) {
        pr[t] = sm[0][t] + sm[1][t] + sm[2][t] + sm[3][t];
        xt[t] = g_x0[b * HH + t];
    }
    __syncthreads();
    if (t < HH) {
        float a = bmx[t];
        for (int k = 0; k < HH; k++) a = fmaf(pr[k], Wmx[k * HH + t], a);
        xt[HH + t] = a;
    }
    __syncthreads();
    if (t < NC) {
        float l = bfc[t];
        for (int k = 0; k < 2 * HH; k++) l = fmaf(xt[k], Wfc[k * NC + t], l);
        lg[t] = l;
    }
    __syncthreads();
    if (t == 0) {
        float m = -1e30f;
        for (int j = 0; j < NC; j++) m = fmaxf(m, lg[j]);
        float s = 0.0f;
        for (int j = 0; j < NC; j++) s += expf(lg[j] - m);
        s_lse = m + logf(s);
    }
    __syncthreads();
    if (t < NC) out[b * NC + t] = lg[t] - s_lse;
}

// ---------------- launch (multi-stream fork/join inside graph capture) ----------------
extern "C" void kernel_launch(void* const* d_in, const int* in_sizes, int n_in,
                              void* d_out, int out_size) {
    const float* x    = (const float*)d_in[0];
    const int*   ei   = (const int*)  d_in[1];
    const float* img  = (const float*)d_in[2];
    const int*   batch= (const int*)  d_in[3];
    const float* W1   = (const float*)d_in[4];
    const float* b1   = (const float*)d_in[5];
    const float* W2   = (const float*)d_in[6];
    const float* b2   = (const float*)d_in[7];
    const float* Wm0  = (const float*)d_in[8];
    const float* bm0  = (const float*)d_in[9];
    const float* Wm1  = (const float*)d_in[10];
    const float* bm1  = (const float*)d_in[11];
    const float* Wmx  = (const float*)d_in[12];
    const float* bmx  = (const float*)d_in[13];
    const float* Wfc  = (const float*)d_in[14];
    const float* bfc  = (const float*)d_in[15];
    float* out = (float*)d_out;
    const int* src = ei;
    const int* dst = ei + NE;

    __half *p_hp1h, *p_hp2h, *p_a1h;
    float *p_a2, *p_x0a, *p_x0, *p_dinv;
    cudaGetSymbolAddress((void**)&p_hp1h, g_hp1h);
    cudaGetSymbolAddress((void**)&p_a1h,  g_a1h);
    cudaGetSymbolAddress((void**)&p_hp2h, g_hp2h);
    cudaGetSymbolAddress((void**)&p_a2,   g_a2);
    cudaGetSymbolAddress((void**)&p_x0a,  g_x0a);
    cudaGetSymbolAddress((void**)&p_x0,   g_x0);
    cudaGetSymbolAddress((void**)&p_dinv, g_dinv);

    static cudaStream_t s1 = nullptr, s2 = nullptr;
    static cudaEvent_t evF = nullptr, evD = nullptr, ev1 = nullptr, ev2 = nullptr;
    if (!s1) {
        cudaStreamCreateWithFlags(&s1, cudaStreamNonBlocking);
        cudaStreamCreateWithFlags(&s2, cudaStreamNonBlocking);
        cudaEventCreateWithFlags(&evF, cudaEventDisableTiming);
        cudaEventCreateWithFlags(&evD, cudaEventDisableTiming);
        cudaEventCreateWithFlags(&ev1, cudaEventDisableTiming);
        cudaEventCreateWithFlags(&ev2, cudaEventDisableTiming);
    }

    // --- main stream: init, then fork ---
    init_kernel<<<(NN + 255) / 256, 256>>>(bm0, bm1);            // 1
    cudaEventRecord(evF, 0);
    cudaStreamWaitEvent(s1, evF, 0);
    cudaStreamWaitEvent(s2, evF, 0);

    deg_kernel <<<(NE + 255) / 256, 256>>>(dst);                 // 2 (main)
    scan1_kernel<<<98, 1024>>>();                                // 3 (main)

    // 4th submission = fp16 tensor-core image GEMM (profiled slot)
    // x0a(=bm0) += img @ Wm0   [64,50176]@[50176,1024], split-K 56x896, 3 CTA/SM
    {
        dim3 grid(MLP0 / 128, 1, 56);
        mma_gemm_kernel<128, true, false, false, false, 3><<<grid, 256, 0, s2>>>(
            img, IMGF, Wm0, MLP0, p_x0a, MLP0, NG, IMGF, 896, nullptr);
    }

    gstart_kernel<<<1, NG + 1, 0, s1>>>(batch);                  // 5 (s1, only needs batch)

    scan2_kernel<<<1, 128>>>();                                  // 6 (main)
    scan3_kernel<<<98, 1024>>>();                                // 7 (main) -> dinv ready
    cudaEventRecord(evD, 0);
    cudaStreamWaitEvent(s1, evD, 0);

    fill_kernel<<<(NE + 255) / 256, 256>>>(src, dst);            // 8 (main)

    // s1: transform1 via fp16 MMA, dinv-scaled fp16 out: hp1' = dinv .* (x @ W1)
    {
        dim3 grid(1, (NN + 63) / 64, 1);
        mma_gemm_kernel<128, false, true, false, true, 1><<<grid, 256, 0, s1>>>(
            x, FIN, W1, H2, (float*)p_hp1h, H2, NN, FIN, FIN, p_dinv);
    }
    cudaEventRecord(ev1, s1);

    // s2: x0(=bm1) += x0a @ Wm1   [64,1024]@[1024,64], split-K 16
    {
        dim3 grid(1, 1, 16);
        gemm3_kernel<64, 64, 4, 4, true><<<grid, 256, 0, s2>>>(
            p_x0a, MLP0, Wm1, HH, p_x0, HH, NG, HH, MLP0, MLP0 / 16);
    }
    cudaEventRecord(ev2, s2);

    // join s1 into main, then conv chain
    cudaStreamWaitEvent(0, ev1, 0);
    agg128_kernel<<<(NN * 32 + 255) / 256, 256>>>(p_hp1h, b1, p_a1h);

    // transform2 via fp16 MMA (BN=64, fp16 A, dinv-scaled fp16 out): hp2' = dinv .* (a1 @ W2)
    {
        dim3 grid(1, (NN + 63) / 64, 1);
        mma_gemm_kernel<64, false, true, true, true, 1><<<grid, 256>>>(
            p_a1h, H2, W2, HH, (float*)p_hp2h, HH, NN, H2, H2, p_dinv);
    }
    agg64_kernel<<<(NN * 32 + 255) / 256, 256>>>(p_hp2h, b2, p_a2);

    // join s2 into main, then fused pool+head
    cudaStreamWaitEvent(0, ev2, 0);
    final_kernel<<<NG, 256>>>(Wmx, bmx, Wfc, bfc, out);
}